// round 3
// baseline (speedup 1.0000x reference)
#include <cuda_runtime.h>
#include <cstdint>

#define BATCH 256
#define CH    2048
#define HW    196
#define NEXP  16
#define NA    3000
#define KDIM  2048

#define MT    16          // batches per tile
#define MAXTILES 32
#define BKT   256         // k per pipeline stage
#define NKT   (KDIM/BKT)  // 8 stages
#define PT    20          // att_t pitch in floats (conflict-free lane stride)
#define AROWS 64          // a-rows per CTA (8 warps x 8 rows)

__device__ float g_attended[BATCH * CH];
__device__ int   g_perm[BATCH];
__device__ int   g_tile_e[MAXTILES];
__device__ int   g_tile_m0[MAXTILES];
__device__ int   g_tile_cnt[MAXTILES];
__device__ int   g_numtiles;
__device__ __align__(16) float g_stage[MAXTILES][KDIM][PT];  // 5.24 MB scratch

// ---- packed f32x2 helpers (sm_103a FFMA2 via PTX) -------------------------
__device__ __forceinline__ unsigned long long fma2(unsigned long long a,
                                                   unsigned long long b,
                                                   unsigned long long c) {
    unsigned long long d;
    asm("fma.rn.f32x2 %0, %1, %2, %3;" : "=l"(d) : "l"(a), "l"(b), "l"(c));
    return d;
}
__device__ __forceinline__ float2 unpack2(unsigned long long v) {
    float2 f;
    asm("mov.b64 {%0,%1}, %2;" : "=f"(f.x), "=f"(f.y) : "l"(v));
    return f;
}
__device__ __forceinline__ unsigned long long bcast2(float v) {
    unsigned long long d;
    asm("mov.b64 %0, {%1, %1};" : "=l"(d) : "f"(v));
    return d;
}
// ---- cp.async helpers -----------------------------------------------------
__device__ __forceinline__ void cp16(void* sdst, const void* gsrc) {
    uint32_t s = (uint32_t)__cvta_generic_to_shared(sdst);
    asm volatile("cp.async.cg.shared.global [%0], [%1], 16;\n" :: "r"(s), "l"(gsrc));
}
__device__ __forceinline__ void cp_commit() {
    asm volatile("cp.async.commit_group;\n" ::: "memory");
}
__device__ __forceinline__ void cp_wait1() {
    asm volatile("cp.async.wait_group 1;\n" ::: "memory");
}
__device__ __forceinline__ void cp_wait0() {
    asm volatile("cp.async.wait_group 0;\n" ::: "memory");
}

// ---------------------------------------------------------------------------
// Kernel 1: masked weighted average pool (DRAM-bound, at floor).
// ---------------------------------------------------------------------------
__global__ void pool_kernel(const float* __restrict__ mask,
                            const float* __restrict__ feat) {
    int b   = blockIdx.x;
    int tid = threadIdx.x;
    int wid = tid >> 5, lane = tid & 31;

    __shared__ __align__(16) float m_s[HW];
    __shared__ float warp_sum[8];
    __shared__ float s_inv;

    float v = 0.f;
    if (tid < HW) {
        v = mask[b * HW + tid] + 1e-10f;
        m_s[tid] = v;
    }
    #pragma unroll
    for (int o = 16; o > 0; o >>= 1) v += __shfl_down_sync(0xffffffffu, v, o);
    if (lane == 0) warp_sum[wid] = v;
    __syncthreads();
    if (tid == 0) {
        float s = 0.f;
        #pragma unroll
        for (int i = 0; i < 8; i++) s += warp_sum[i];
        s_inv = 1.0f / s;
    }
    __syncthreads();
    float inv = s_inv;

    const float4* m4 = (const float4*)m_s;
    float4 mA = m4[lane];
    float4 mB = (lane < 17) ? m4[lane + 32] : make_float4(0.f, 0.f, 0.f, 0.f);

    int cbase = blockIdx.y * 256 + wid * 32;
    for (int it = 0; it < 32; it++) {
        int c = cbase + it;
        const float4* row = (const float4*)(feat + ((size_t)b * CH + c) * HW);
        float4 f = row[lane];
        float s = f.x * mA.x + f.y * mA.y + f.z * mA.z + f.w * mA.w;
        if (lane < 17) {
            float4 f2 = row[lane + 32];
            s += f2.x * mB.x + f2.y * mB.y + f2.z * mB.z + f2.w * mB.w;
        }
        #pragma unroll
        for (int o = 16; o > 0; o >>= 1) s += __shfl_down_sync(0xffffffffu, s, o);
        if (lane == 0) g_attended[b * CH + c] = s * inv;
    }
}

// ---------------------------------------------------------------------------
// Kernel 2: group batches by expert, build tiles of <=16 batches.
// ---------------------------------------------------------------------------
__global__ void group_kernel(const void* __restrict__ inst) {
    int tid = threadIdx.x;
    __shared__ int odd_nz;
    __shared__ int sh_e[BATCH];
    __shared__ int cnt[NEXP];
    __shared__ int off[NEXP + 1];

    if (tid == 0) odd_nz = 0;
    __syncthreads();
    const int* iv = (const int*)inst;
    if (tid < BATCH / 2 && iv[2 * tid + 1] != 0) atomicExch(&odd_nz, 1);
    __syncthreads();

    int e;
    if (odd_nz == 0) e = (int)((const long long*)inst)[tid];
    else             e = iv[tid];

    sh_e[tid] = e;
    if (tid < NEXP) cnt[tid] = 0;
    __syncthreads();

    atomicAdd(&cnt[e], 1);
    int rank = 0;
    for (int j = 0; j < tid; j++) rank += (sh_e[j] == e);
    __syncthreads();

    if (tid == 0) {
        off[0] = 0;
        for (int i = 0; i < NEXP; i++) off[i + 1] = off[i] + cnt[i];
        int nt = 0;
        for (int ei = 0; ei < NEXP; ei++)
            for (int s = 0; s < cnt[ei]; s += MT) {
                g_tile_e[nt]   = ei;
                g_tile_m0[nt]  = off[ei] + s;
                g_tile_cnt[nt] = min(MT, cnt[ei] - s);
                nt++;
            }
        g_numtiles = nt;
    }
    __syncthreads();
    g_perm[off[e] + rank] = tid;
}

// ---------------------------------------------------------------------------
// Kernel 3: stage transposed attended panels per tile:
//   g_stage[tile][k][b] = g_attended[perm[m0+b]][k]   (b clamped, pitch 20)
// grid (NKT, MAXTILES) x 256 threads; chunk = 256 k.
// ---------------------------------------------------------------------------
__global__ void stage_kernel() {
    int tile = blockIdx.y;
    if (tile >= g_numtiles) return;
    int k0 = blockIdx.x * BKT;
    int tid = threadIdx.x;

    __shared__ float s[MT][BKT + 4];
    __shared__ int s_bb[MT];
    if (tid < MT) {
        int m0 = g_tile_m0[tile], mcnt = g_tile_cnt[tile];
        s_bb[tid] = g_perm[m0 + min(tid, mcnt - 1)];
    }
    __syncthreads();

    // load 16 x 256 panel (coalesced float4)
    int b = tid >> 4, f = tid & 15;
    const float* src = g_attended + (size_t)s_bb[b] * KDIM + k0;
    #pragma unroll
    for (int j = 0; j < 4; j++) {
        float4 v = *(const float4*)(src + (f + 16 * j) * 4);
        *(float4*)&s[b][(f + 16 * j) * 4] = v;
    }
    __syncthreads();

    // transposed write: thread = one k, gathers 16 b (conflict-free LDS.32)
    int k = tid;
    float o[PT];
    #pragma unroll
    for (int bi = 0; bi < MT; bi++) o[bi] = s[bi][k];
    #pragma unroll
    for (int bi = MT; bi < PT; bi++) o[bi] = 0.f;
    float* dst = &g_stage[tile][k0 + k][0];
    #pragma unroll
    for (int q = 0; q < PT / 4; q++)
        *(float4*)(dst + q * 4) = *(float4*)&o[q * 4];
}

// ---------------------------------------------------------------------------
// Kernel 4: W-stationary grouped GEMM, FFMA2 over b-pairs.
// CTA: 256 thr / 8 warps; warp owns 8 a-rows; lane l owns k = l (mod 32).
// Dynamic smem: Ws[2][64][256] (128KB) + At[2][256][20] (40KB) = 172KB.
// cp.async double-buffered pipeline over 8 k-stages of 256.
// ---------------------------------------------------------------------------
__global__ __launch_bounds__(256, 1)
void gemm_kernel(const float* __restrict__ W,
                 const float* __restrict__ bias,
                 float* __restrict__ out) {
    int tile = blockIdx.y;
    if (tile >= g_numtiles) return;

    int e    = g_tile_e[tile];
    int m0   = g_tile_m0[tile];
    int mcnt = g_tile_cnt[tile];
    int a0   = blockIdx.x * AROWS;
    int tid  = threadIdx.x;
    int wid  = tid >> 5, lane = tid & 31;

    extern __shared__ float dsm[];
    float* Ws = dsm;                       // [2][64][256]
    float* At = dsm + 2 * AROWS * BKT;     // [2][256][PT]

    __shared__ int s_bb[MT];
    if (tid < MT) s_bb[tid] = g_perm[m0 + min(tid, mcnt - 1)];

    // ---- loader addressing ----
    int lrow = tid >> 2;                 // 0..63 W row
    int lq0  = tid & 3;
    int la   = a0 + lrow; la = (la < NA) ? la : (NA - 1);
    const float* wsrc = W + ((size_t)e * NA + la) * KDIM;
    const float* asrc = &g_stage[tile][0][0];

    // stage loader: W 16x16B + att 5x16B per thread
    auto load_stage = [&](int s, int buf) {
        const float* ws = wsrc + s * BKT;
        float* wd = Ws + buf * AROWS * BKT + lrow * BKT;
        #pragma unroll
        for (int j = 0; j < 16; j++)
            cp16(wd + (lq0 + 4 * j) * 4, ws + (lq0 + 4 * j) * 4);
        const float* as = asrc + s * BKT * PT;
        float* ad = At + buf * BKT * PT;
        #pragma unroll
        for (int j = 0; j < 5; j++)
            cp16(ad + (tid + 256 * j) * 4, as + (tid + 256 * j) * 4);
    };

    load_stage(0, 0); cp_commit();
    load_stage(1, 1); cp_commit();

    unsigned long long acc[8][8];
    #pragma unroll
    for (int r = 0; r < 8; r++)
        #pragma unroll
        for (int p = 0; p < 8; p++) acc[r][p] = 0ull;

    for (int kt = 0; kt < NKT; kt++) {
        if (kt < NKT - 1) cp_wait1(); else cp_wait0();
        __syncthreads();

        int buf = kt & 1;
        const float* atb = At + buf * BKT * PT;
        const float* wsb = Ws + buf * AROWS * BKT + (wid * 8) * BKT;

        #pragma unroll 4
        for (int i = 0; i < 8; i++) {
            int kk = i * 32 + lane;
            const ulonglong2* tp = (const ulonglong2*)(atb + kk * PT);
            ulonglong2 t0 = tp[0], t1 = tp[1], t2 = tp[2], t3 = tp[3];
            unsigned long long tt[8] = {t0.x, t0.y, t1.x, t1.y,
                                        t2.x, t2.y, t3.x, t3.y};
            #pragma unroll
            for (int r = 0; r < 8; r++) {
                unsigned long long wp = bcast2(wsb[r * BKT + kk]);
                #pragma unroll
                for (int p = 0; p < 8; p++)
                    acc[r][p] = fma2(wp, tt[p], acc[r][p]);
            }
        }
        __syncthreads();
        if (kt + 2 < NKT) { load_stage(kt + 2, buf); cp_commit(); }
        else if (kt < NKT - 1) { cp_commit(); }   // keep group count in step
    }

    // ---- epilogue: butterfly-reduce over lanes, scatter with bias ----
    float res[4];
    #pragma unroll
    for (int r = 0; r < 8; r++) {
        #pragma unroll
        for (int p = 0; p < 8; p++) {
            float2 f = unpack2(acc[r][p]);
            #pragma unroll
            for (int o = 16; o > 0; o >>= 1) {
                f.x += __shfl_xor_sync(0xffffffffu, f.x, o);
                f.y += __shfl_xor_sync(0xffffffffu, f.y, o);
            }
            int o0 = r * 16 + 2 * p;      // output index 0..127
            if (lane == (o0 & 31))       res[o0 >> 5] = f.x;
            if (lane == ((o0 + 1) & 31)) res[(o0 + 1) >> 5] = f.y;
        }
    }
    #pragma unroll
    for (int h = 0; h < 4; h++) {
        int o = h * 32 + lane;
        int r = o >> 4, b = o & 15;
        int a = a0 + wid * 8 + r;
        if (b < mcnt && a < NA)
            out[(size_t)s_bb[b] * NA + a] = res[h] + bias[e * NA + a];
    }
}

// ---------------------------------------------------------------------------
extern "C" void kernel_launch(void* const* d_in, const int* in_sizes, int n_in,
                              void* d_out, int out_size) {
    const float* mask = (const float*)d_in[0];
    const float* feat = (const float*)d_in[1];
    const float* W    = (const float*)d_in[2];
    const float* bias = (const float*)d_in[3];
    const void*  inst = d_in[4];
    float* out = (float*)d_out;

    const int GEMM_SMEM = (2 * AROWS * BKT + 2 * BKT * PT) * 4;  // 172032 B
    cudaFuncSetAttribute(gemm_kernel,
                         cudaFuncAttributeMaxDynamicSharedMemorySize, GEMM_SMEM);

    pool_kernel<<<dim3(BATCH, 8), 256>>>(mask, feat);
    group_kernel<<<1, BATCH>>>(inst);
    stage_kernel<<<dim3(NKT, MAXTILES), 256>>>();
    gemm_kernel<<<dim3((NA + AROWS - 1) / AROWS, MAXTILES), 256, GEMM_SMEM>>>(
        W, bias, out);
}